// round 10
// baseline (speedup 1.0000x reference)
#include <cuda_runtime.h>
#include <cuda_fp16.h>
#include <cstdint>

#define TILE 64
#define NT   128

// smem/blob byte offsets. B tiles: 64 rows x 128 B, SW128 swizzle.
#define S_BH   0        // R[j][k] hi fp16      (GEMM1 B)
#define S_BL   8192     // (R - hi)*2048 fp16   (GEMM1 B lo)
#define S_RT   16384    // R^T hi fp16 [kout][j] (GEMM2 B)
#define S_CB   24576    // float[16]
#define S_BND  24640    // float[15] + pad
#define BLOB_BYTES 24704
#define S_OUT  24704    // 4 warps x 4096 B out-scratch
#define SMEM_BYTES (S_OUT + 4 * 4096)

#define INV2048 4.8828125e-4f

static __device__ __align__(16) unsigned char g_blob[BLOB_BYTES];

static __device__ __forceinline__ uint32_t smem_u32(const void* p) {
    uint32_t a;
    asm("{ .reg .u64 t; cvta.to.shared.u64 t, %1; cvt.u32.u64 %0, t; }" : "=r"(a) : "l"(p));
    return a;
}
// byte offset of fp16 (row, col) in a [*][64] fp16 tile with SW128 swizzle
static __device__ __forceinline__ int sw(int row, int col) {
    return row * 128 + ((col * 2) ^ ((row & 7) << 4));
}
static __device__ __forceinline__ uint32_t h2u(__half2 h) {
    return *reinterpret_cast<uint32_t*>(&h);
}
static __device__ __forceinline__ void ldsm4(uint32_t* r, uint32_t addr) {
    asm volatile("ldmatrix.sync.aligned.m8n8.x4.shared.b16 {%0,%1,%2,%3}, [%4];"
        : "=r"(r[0]), "=r"(r[1]), "=r"(r[2]), "=r"(r[3]) : "r"(addr));
}
static __device__ __forceinline__ void mma16816(float* c, const uint32_t* a,
                                                uint32_t b0, uint32_t b1) {
    asm volatile("mma.sync.aligned.m16n8k16.row.col.f32.f16.f16.f32 "
        "{%0,%1,%2,%3}, {%4,%5,%6,%7}, {%8,%9}, {%0,%1,%2,%3};"
        : "+f"(c[0]), "+f"(c[1]), "+f"(c[2]), "+f"(c[3])
        : "r"(a[0]), "r"(a[1]), "r"(a[2]), "r"(a[3]), "r"(b0), "r"(b1));
}

// one-shot: build the staged smem image (B tiles + quantizer tables) in global
__global__ void tq_setup(const float* __restrict__ Rg, const float* __restrict__ cb) {
    int t = threadIdx.x;
    for (int i = t; i < 4096; i += 256) {
        int j = i >> 6, k = i & 63;
        float v = Rg[i];
        __half hv = __float2half_rn(v);
        __half lv = __float2half_rn((v - __half2float(hv)) * 2048.0f);
        *(__half*)(g_blob + S_BH + sw(j, k)) = hv;
        *(__half*)(g_blob + S_BL + sw(j, k)) = lv;
        *(__half*)(g_blob + S_RT + sw(k, j)) = hv;
    }
    if (t < 16) ((float*)(g_blob + S_CB))[t] = cb[t];
    if (t < 15) ((float*)(g_blob + S_BND))[t] = 0.5f * (cb[t] + cb[t + 1]);
}

__global__ void __launch_bounds__(NT, 5)
tq_mma_kernel(const float* __restrict__ x, float* __restrict__ out, int nrows)
{
    extern __shared__ char smem[];
    const uint32_t sb = smem_u32(smem);

    const int t   = threadIdx.x;
    const int wid = t >> 5;
    const int l   = t & 31;
    const int g   = l >> 2;      // fragment row group 0..7
    const int tq  = l & 3;       // fragment quad col
    const long long row0 = (long long)blockIdx.x * TILE;

    // ---- copy staged image into smem (bulk float4) ----
    {
        const float4* src = (const float4*)g_blob;
        float4* dst = (float4*)smem;
        #pragma unroll
        for (int i = t; i < BLOB_BYTES / 16; i += NT) dst[i] = src[i];
    }

    // ---- load x directly in fragment layout: rows rowA, rowA+8; cols {8m+2tq} ----
    const int rowA = wid * 16 + g;
    long long grow0 = row0 + rowA;
    long long grow1 = grow0 + 8;
    long long gr0 = grow0 < nrows ? grow0 : (long long)nrows - 1;
    long long gr1 = grow1 < nrows ? grow1 : (long long)nrows - 1;

    float2 v0[8], v1[8];
    float ss0 = 0.f, ss1 = 0.f;
    #pragma unroll
    for (int m = 0; m < 8; m++) {
        v0[m] = *(const float2*)(x + gr0 * 64 + 8 * m + 2 * tq);
        v1[m] = *(const float2*)(x + gr1 * 64 + 8 * m + 2 * tq);
        ss0 += v0[m].x * v0[m].x + v0[m].y * v0[m].y;
        ss1 += v1[m].x * v1[m].x + v1[m].y * v1[m].y;
    }
    ss0 += __shfl_xor_sync(0xffffffffu, ss0, 1);
    ss0 += __shfl_xor_sync(0xffffffffu, ss0, 2);
    ss1 += __shfl_xor_sync(0xffffffffu, ss1, 1);
    ss1 += __shfl_xor_sync(0xffffffffu, ss1, 2);
    float scale0 = fmaxf(sqrtf(ss0), 1e-8f);
    float scale1 = fmaxf(sqrtf(ss1), 1e-8f);
    float inv0 = 1.0f / scale0;
    float inv1 = 1.0f / scale1;

    // split hi / scaled-lo into half2 registers (fragment order: m = k-pair)
    uint32_t xh0[8], xl0[8], xh1[8], xl1[8];
    #pragma unroll
    for (int m = 0; m < 8; m++) {
        float a0 = v0[m].x * inv0, a1 = v0[m].y * inv0;
        float b0 = v1[m].x * inv1, b1 = v1[m].y * inv1;
        __half2 h0 = __floats2half2_rn(a0, a1);
        __half2 h1 = __floats2half2_rn(b0, b1);
        float2 hf0 = __half22float2(h0), hf1 = __half22float2(h1);
        xh0[m] = h2u(h0);
        xh1[m] = h2u(h1);
        xl0[m] = h2u(__floats2half2_rn((a0 - hf0.x) * 2048.0f, (a1 - hf0.y) * 2048.0f));
        xl1[m] = h2u(__floats2half2_rn((b0 - hf1.x) * 2048.0f, (b1 - hf1.y) * 2048.0f));
    }
    __syncthreads();   // staged image ready

    // quantizer tree boundary regs (levels 1-3)
    const float* sBnd = (const float*)(smem + S_BND);
    const float m1 = sBnd[1], m3 = sBnd[3], m5 = sBnd[5], m7 = sBnd[7];
    const float m9 = sBnd[9], m11 = sBnd[11], m13 = sBnd[13];

    // ---- LDSM lane addressing (shared by all three B tiles) ----
    const int tl  = l >> 3;
    const int rwi = l & 7;
    const int rsel = ((tl & 2) << 2) + rwi;
    const int cbyte = (tl & 1) << 4;
    const int swz = rwi << 4;
    int lo[4];
    #pragma unroll
    for (int ch = 0; ch < 4; ch++) lo[ch] = rsel * 128 + ((ch * 32 + cbyte) ^ swz);

    // ---- fused GEMM1 -> quantize -> GEMM2, 16 output cols (ntp block) at a time ----
    float d[8][4];
    #pragma unroll
    for (int nt = 0; nt < 8; nt++)
        #pragma unroll
        for (int i = 0; i < 4; i++) d[nt][i] = 0.f;

    #pragma unroll
    for (int ntp = 0; ntp < 4; ntp++) {
        float c1[2][4], c2[2][4];
        #pragma unroll
        for (int s = 0; s < 2; s++)
            #pragma unroll
            for (int i = 0; i < 4; i++) { c1[s][i] = 0.f; c2[s][i] = 0.f; }

        #pragma unroll
        for (int ch = 0; ch < 4; ch++) {
            uint32_t bh[4], bl[4];
            ldsm4(bh, sb + S_BH + ntp * 2048 + lo[ch]);
            ldsm4(bl, sb + S_BL + ntp * 2048 + lo[ch]);
            uint32_t ah[4] = { xh0[2*ch], xh1[2*ch], xh0[2*ch+1], xh1[2*ch+1] };
            uint32_t al[4] = { xl0[2*ch], xl1[2*ch], xl0[2*ch+1], xl1[2*ch+1] };
            mma16816(c1[0], ah, bh[0], bh[1]);
            mma16816(c2[0], ah, bl[0], bl[1]);
            mma16816(c2[0], al, bh[0], bh[1]);
            mma16816(c1[1], ah, bh[2], bh[3]);
            mma16816(c2[1], ah, bl[2], bl[3]);
            mma16816(c2[1], al, bh[2], bh[3]);
        }

        // quantize this 16-col block; E block = GEMM2 k-chunk ntp
        uint32_t ae[4];
        #pragma unroll
        for (int s = 0; s < 2; s++) {
            float e[4];
            #pragma unroll
            for (int i = 0; i < 4; i++) {
                float z = c1[s][i] + c2[s][i] * INV2048;
                bool cA = z > m7;
                float b2 = cA ? m11 : m3;
                bool cB = z > b2;
                float b3 = cA ? (cB ? m13 : m9) : (cB ? m5 : m1);
                bool cC = z > b3;
                int off = (cA ? 32 : 0) + (cB ? 16 : 0) + (cC ? 8 : 0);
                float b4 = *(const float*)(smem + S_BND + off);
                int voff = off + ((z > b4) ? 4 : 0);
                float q = *(const float*)(smem + S_CB + voff);
                e[i] = q - z;
            }
            ae[2*s]   = h2u(__floats2half2_rn(e[0], e[1]));
            ae[2*s+1] = h2u(__floats2half2_rn(e[2], e[3]));
        }

        #pragma unroll
        for (int ntp2 = 0; ntp2 < 4; ntp2++) {
            uint32_t br[4];
            ldsm4(br, sb + S_RT + ntp2 * 2048 + lo[ntp]);
            mma16816(d[2*ntp2],   ae, br[0], br[1]);
            mma16816(d[2*ntp2+1], ae, br[2], br[3]);
        }
    }

    // ---- epilogue: y = xn + E@R, rescale; recoalesce via warp-private scratch ----
    {
        char* ob = smem + S_OUT + wid * 4096;   // [16 rows][256 B], swizzled
        #pragma unroll
        for (int nt = 0; nt < 8; nt++) {
            float2 h0 = __half22float2(*reinterpret_cast<__half2*>(&xh0[nt]));
            float2 l0 = __half22float2(*reinterpret_cast<__half2*>(&xl0[nt]));
            float2 h1 = __half22float2(*reinterpret_cast<__half2*>(&xh1[nt]));
            float2 l1 = __half22float2(*reinterpret_cast<__half2*>(&xl1[nt]));
            int bc = 32 * nt + 8 * tq;   // byte col
            float2 o0, o1;
            o0.x = (h0.x + l0.x * INV2048 + d[nt][0]) * scale0;
            o0.y = (h0.y + l0.y * INV2048 + d[nt][1]) * scale0;
            o1.x = (h1.x + l1.x * INV2048 + d[nt][2]) * scale1;
            o1.y = (h1.y + l1.y * INV2048 + d[nt][3]) * scale1;
            int r0 = g, r1 = g + 8;
            *(float2*)(ob + r0 * 256 + (bc ^ ((r0 & 3) * 32))) = o0;
            *(float2*)(ob + r1 * 256 + (bc ^ ((r1 & 3) * 32))) = o1;
        }
        __syncwarp();
        #pragma unroll
        for (int i = 0; i < 8; i++) {
            int rr = 2 * i + (l >> 4);
            int q4 = l & 15;
            float4 vv = *(const float4*)(ob + rr * 256 + ((q4 * 16) ^ ((rr & 3) * 32)));
            long long gout = row0 + wid * 16 + rr;
            if (gout < nrows) *(float4*)(out + gout * 64 + q4 * 4) = vv;
        }
    }
}

extern "C" void kernel_launch(void* const* d_in, const int* in_sizes, int n_in,
                              void* d_out, int out_size)
{
    const float* x  = (const float*)d_in[0];   // [2,32,4096,64] fp32
    const float* cb = (const float*)d_in[1];   // [16] fp32, sorted
    const float* Rg = (const float*)d_in[2];   // [64,64] fp32
    float* out = (float*)d_out;

    int nrows = in_sizes[0] / 64;
    int blocks = (nrows + TILE - 1) / TILE;

    tq_setup<<<1, 256>>>(Rg, cb);
    cudaFuncSetAttribute(tq_mma_kernel, cudaFuncAttributeMaxDynamicSharedMemorySize, SMEM_BYTES);
    tq_mma_kernel<<<blocks, NT, SMEM_BYTES>>>(x, out, nrows);
}

// round 11
// speedup vs baseline: 1.2478x; 1.2478x over previous
#include <cuda_runtime.h>
#include <cuda_fp16.h>
#include <cstdint>

#define TILE 128
#define NT   256

// smem byte offsets. B tiles: 64 rows x 128 B, SW128 swizzle.
#define S_BH   0        // R[j][k] hi fp16      (GEMM1 B)
#define S_BL   8192     // (R - hi)*2048 fp16   (GEMM1 B lo)
#define S_RT   16384    // R^T hi fp16 [kout][j] (GEMM2 B)
#define S_CB   24576    // float[16]
#define S_BND  24640    // float[15] + pad
#define S_OUT  24704    // 8 warps x 4096 B out-scratch
#define SMEM_BYTES (S_OUT + 8 * 4096)

#define INV2048 4.8828125e-4f

static __device__ __forceinline__ uint32_t smem_u32(const void* p) {
    uint32_t a;
    asm("{ .reg .u64 t; cvta.to.shared.u64 t, %1; cvt.u32.u64 %0, t; }" : "=r"(a) : "l"(p));
    return a;
}
// byte offset of fp16 (row, col) in a [*][64] fp16 tile with SW128 swizzle
static __device__ __forceinline__ int sw(int row, int col) {
    return row * 128 + ((col * 2) ^ ((row & 7) << 4));
}
static __device__ __forceinline__ uint32_t h2u(__half2 h) {
    return *reinterpret_cast<uint32_t*>(&h);
}
static __device__ __forceinline__ void ldsm4(uint32_t* r, uint32_t addr) {
    asm volatile("ldmatrix.sync.aligned.m8n8.x4.shared.b16 {%0,%1,%2,%3}, [%4];"
        : "=r"(r[0]), "=r"(r[1]), "=r"(r[2]), "=r"(r[3]) : "r"(addr));
}
static __device__ __forceinline__ void mma16816(float* c, const uint32_t* a,
                                                uint32_t b0, uint32_t b1) {
    asm volatile("mma.sync.aligned.m16n8k16.row.col.f32.f16.f16.f32 "
        "{%0,%1,%2,%3}, {%4,%5,%6,%7}, {%8,%9}, {%0,%1,%2,%3};"
        : "+f"(c[0]), "+f"(c[1]), "+f"(c[2]), "+f"(c[3])
        : "r"(a[0]), "r"(a[1]), "r"(a[2]), "r"(a[3]), "r"(b0), "r"(b1));
}

__global__ void __launch_bounds__(NT, 2)
tq_mma_kernel(const float* __restrict__ x, const float* __restrict__ cb,
              const float* __restrict__ Rg, float* __restrict__ out, int nrows)
{
    extern __shared__ char smem[];
    const uint32_t sb = smem_u32(smem);
    float* sCb  = (float*)(smem + S_CB);
    float* sBnd = (float*)(smem + S_BND);

    const int t   = threadIdx.x;
    const int wid = t >> 5;
    const int l   = t & 31;
    const int g   = l >> 2;      // fragment row group 0..7
    const int tq  = l & 3;       // fragment quad col
    const long long row0 = (long long)blockIdx.x * TILE;

    // ---- stage R: hi / scaled-lo (GEMM1 B), hi-transpose (GEMM2 B) ----
    #pragma unroll 4
    for (int i = t; i < 4096; i += NT) {
        int j = i >> 6, k = i & 63;
        float v = Rg[i];
        __half hv = __float2half_rn(v);
        __half lv = __float2half_rn((v - __half2float(hv)) * 2048.0f);
        *(__half*)(smem + S_BH + sw(j, k)) = hv;
        *(__half*)(smem + S_BL + sw(j, k)) = lv;
        *(__half*)(smem + S_RT + sw(k, j)) = hv;
    }
    if (t < 16) sCb[t] = cb[t];
    if (t < 15) sBnd[t] = 0.5f * (cb[t] + cb[t + 1]);

    // ---- load x directly in fragment layout: rows rowA, rowA+8; cols {8m+2tq} ----
    const int rowA = wid * 16 + g;
    long long grow0 = row0 + rowA;
    long long grow1 = grow0 + 8;
    long long gr0 = grow0 < nrows ? grow0 : (long long)nrows - 1;
    long long gr1 = grow1 < nrows ? grow1 : (long long)nrows - 1;

    float2 v0[8], v1[8];
    float ss0 = 0.f, ss1 = 0.f;
    #pragma unroll
    for (int m = 0; m < 8; m++) {
        v0[m] = *(const float2*)(x + gr0 * 64 + 8 * m + 2 * tq);
        v1[m] = *(const float2*)(x + gr1 * 64 + 8 * m + 2 * tq);
        ss0 += v0[m].x * v0[m].x + v0[m].y * v0[m].y;
        ss1 += v1[m].x * v1[m].x + v1[m].y * v1[m].y;
    }
    ss0 += __shfl_xor_sync(0xffffffffu, ss0, 1);
    ss0 += __shfl_xor_sync(0xffffffffu, ss0, 2);
    ss1 += __shfl_xor_sync(0xffffffffu, ss1, 1);
    ss1 += __shfl_xor_sync(0xffffffffu, ss1, 2);
    float scale0 = fmaxf(sqrtf(ss0), 1e-8f);
    float scale1 = fmaxf(sqrtf(ss1), 1e-8f);
    float inv0 = 1.0f / scale0;
    float inv1 = 1.0f / scale1;

    // split hi / scaled-lo into half2 registers (fragment order: m = k-pair)
    uint32_t xh0[8], xl0[8], xh1[8], xl1[8];
    #pragma unroll
    for (int m = 0; m < 8; m++) {
        float a0 = v0[m].x * inv0, a1 = v0[m].y * inv0;
        float b0 = v1[m].x * inv1, b1 = v1[m].y * inv1;
        __half2 h0 = __floats2half2_rn(a0, a1);
        __half2 h1 = __floats2half2_rn(b0, b1);
        float2 hf0 = __half22float2(h0), hf1 = __half22float2(h1);
        xh0[m] = h2u(h0);
        xh1[m] = h2u(h1);
        xl0[m] = h2u(__floats2half2_rn((a0 - hf0.x) * 2048.0f, (a1 - hf0.y) * 2048.0f));
        xl1[m] = h2u(__floats2half2_rn((b0 - hf1.x) * 2048.0f, (b1 - hf1.y) * 2048.0f));
    }
    __syncthreads();   // B tiles + tables ready

    // quantizer tree boundary regs (levels 1-3)
    const float m1 = sBnd[1], m3 = sBnd[3], m5 = sBnd[5], m7 = sBnd[7];
    const float m9 = sBnd[9], m11 = sBnd[11], m13 = sBnd[13];

    // ---- LDSM lane addressing (shared by all three B tiles) ----
    const int tl  = l >> 3;
    const int rwi = l & 7;
    const int rsel = ((tl & 2) << 2) + rwi;
    const int cbyte = (tl & 1) << 4;
    const int swz = rwi << 4;
    int lo[4];
    #pragma unroll
    for (int ch = 0; ch < 4; ch++) lo[ch] = rsel * 128 + ((ch * 32 + cbyte) ^ swz);

    // ---- fused GEMM1 -> quantize -> GEMM2, one 16-col ntp block at a time ----
    float d[8][4];
    #pragma unroll
    for (int nt = 0; nt < 8; nt++)
        #pragma unroll
        for (int i = 0; i < 4; i++) d[nt][i] = 0.f;

    #pragma unroll
    for (int ntp = 0; ntp < 4; ntp++) {
        float c1[2][4], c2[2][4];
        #pragma unroll
        for (int s = 0; s < 2; s++)
            #pragma unroll
            for (int i = 0; i < 4; i++) { c1[s][i] = 0.f; c2[s][i] = 0.f; }

        #pragma unroll
        for (int ch = 0; ch < 4; ch++) {
            uint32_t bh[4], bl[4];
            ldsm4(bh, sb + S_BH + ntp * 2048 + lo[ch]);
            ldsm4(bl, sb + S_BL + ntp * 2048 + lo[ch]);
            uint32_t ah[4] = { xh0[2*ch], xh1[2*ch], xh0[2*ch+1], xh1[2*ch+1] };
            uint32_t al[4] = { xl0[2*ch], xl1[2*ch], xl0[2*ch+1], xl1[2*ch+1] };
            mma16816(c1[0], ah, bh[0], bh[1]);
            mma16816(c2[0], ah, bl[0], bl[1]);
            mma16816(c2[0], al, bh[0], bh[1]);
            mma16816(c1[1], ah, bh[2], bh[3]);
            mma16816(c2[1], ah, bl[2], bl[3]);
            mma16816(c2[1], al, bh[2], bh[3]);
        }

        // quantize this 16-col block; E block = GEMM2 k-chunk ntp
        uint32_t ae[4];
        #pragma unroll
        for (int s = 0; s < 2; s++) {
            float e[4];
            #pragma unroll
            for (int i = 0; i < 4; i++) {
                float z = c1[s][i] + c2[s][i] * INV2048;
                bool cA = z > m7;
                float b2 = cA ? m11 : m3;
                bool cB = z > b2;
                float b3 = cA ? (cB ? m13 : m9) : (cB ? m5 : m1);
                bool cC = z > b3;
                int off = (cA ? 32 : 0) + (cB ? 16 : 0) + (cC ? 8 : 0);
                float b4 = *(const float*)(smem + S_BND + off);
                int voff = off + ((z > b4) ? 4 : 0);
                float q = *(const float*)(smem + S_CB + voff);
                e[i] = q - z;
            }
            ae[2*s]   = h2u(__floats2half2_rn(e[0], e[1]));
            ae[2*s+1] = h2u(__floats2half2_rn(e[2], e[3]));
        }

        #pragma unroll
        for (int ntp2 = 0; ntp2 < 4; ntp2++) {
            uint32_t br[4];
            ldsm4(br, sb + S_RT + ntp2 * 2048 + lo[ntp]);
            mma16816(d[2*ntp2],   ae, br[0], br[1]);
            mma16816(d[2*ntp2+1], ae, br[2], br[3]);
        }
    }

    // ---- epilogue: y = xn + E@R, rescale; recoalesce via warp-private scratch ----
    {
        char* ob = smem + S_OUT + wid * 4096;   // [16 rows][256 B], swizzled
        #pragma unroll
        for (int nt = 0; nt < 8; nt++) {
            float2 h0 = __half22float2(*reinterpret_cast<__half2*>(&xh0[nt]));
            float2 l0 = __half22float2(*reinterpret_cast<__half2*>(&xl0[nt]));
            float2 h1 = __half22float2(*reinterpret_cast<__half2*>(&xh1[nt]));
            float2 l1 = __half22float2(*reinterpret_cast<__half2*>(&xl1[nt]));
            int bc = 32 * nt + 8 * tq;   // byte col
            float2 o0, o1;
            o0.x = (h0.x + l0.x * INV2048 + d[nt][0]) * scale0;
            o0.y = (h0.y + l0.y * INV2048 + d[nt][1]) * scale0;
            o1.x = (h1.x + l1.x * INV2048 + d[nt][2]) * scale1;
            o1.y = (h1.y + l1.y * INV2048 + d[nt][3]) * scale1;
            int r0 = g, r1 = g + 8;
            *(float2*)(ob + r0 * 256 + (bc ^ ((r0 & 3) * 32))) = o0;
            *(float2*)(ob + r1 * 256 + (bc ^ ((r1 & 3) * 32))) = o1;
        }
        __syncwarp();
        #pragma unroll
        for (int i = 0; i < 8; i++) {
            int rr = 2 * i + (l >> 4);
            int q4 = l & 15;
            float4 vv = *(const float4*)(ob + rr * 256 + ((q4 * 16) ^ ((rr & 3) * 32)));
            long long gout = row0 + wid * 16 + rr;
            if (gout < nrows) *(float4*)(out + gout * 64 + q4 * 4) = vv;
        }
    }
}

extern "C" void kernel_launch(void* const* d_in, const int* in_sizes, int n_in,
                              void* d_out, int out_size)
{
    const float* x  = (const float*)d_in[0];   // [2,32,4096,64] fp32
    const float* cb = (const float*)d_in[1];   // [16] fp32, sorted
    const float* Rg = (const float*)d_in[2];   // [64,64] fp32
    float* out = (float*)d_out;

    int nrows = in_sizes[0] / 64;
    int blocks = (nrows + TILE - 1) / TILE;

    cudaFuncSetAttribute(tq_mma_kernel, cudaFuncAttributeMaxDynamicSharedMemorySize, SMEM_BYTES);
    tq_mma_kernel<<<blocks, NT, SMEM_BYTES>>>(x, cb, Rg, out, nrows);
}